// round 8
// baseline (speedup 1.0000x reference)
#include <cuda_runtime.h>
#include <cuda_bf16.h>
#include <cstdint>

#define NNODES 4096
#define NEDGES 131072
#define IN_CH 512
#define E_CH 64
#define HID 256
#define OUTD 16
#define NB_E 5
#define NB_Z 3
#define REWEIGHT 0.6454972243679028f

typedef unsigned long long u64;

__device__ int   g_idx64;
__device__ int   g_deg[NNODES];
__device__ int   g_rowptr[NNODES + 1];
__device__ int   g_cursor[NNODES];
__device__ float g_dinv[NNODES];
__device__ int   g_col[NEDGES];
__device__ float g_w[NEDGES];
__device__ float g_h1[NNODES * HID];
__device__ float g_hx[NNODES * HID];
__device__ __nv_bfloat16 g_he16[NB_E * NNODES * HID];
__device__ float g_we32[E_CH * 32];
__device__ float g_bewc[32];
__device__ float g_the[NB_E * NNODES * 32];
__device__ float g_thx[NNODES * 32];
__device__ float g_t[NB_E * NNODES * 32];
__device__ float g_acc[8];

#define OFF_ADJ 0ull
#define OFF_MU  (OFF_ADJ + 3ull * NNODES * NNODES)
#define OFF_SIG (OFF_MU  + (u64)NB_E * NNODES * OUTD)
#define OFF_Z   (OFF_SIG + (u64)NB_E * NNODES * OUTD)
#define OFF_ZS  (OFF_Z   + (u64)NB_Z * NNODES * OUTD)
#define OFF_EPS (OFF_ZS  + (u64)NB_Z * NNODES * OUTD)
#define OFF_RK  (OFF_EPS + (u64)NB_Z * NNODES * OUTD)
#define OFF_SNR (OFF_RK + 16ull)

// ---------- f32x2 helpers ----------
__device__ __forceinline__ u64 pack2(float a, float b) {
    u64 r; asm("mov.b64 %0, {%1, %2};" : "=l"(r) : "r"(__float_as_int(a)), "r"(__float_as_int(b))); return r;
}
__device__ __forceinline__ void unpack2f(u64 v, float& a, float& b) {
    int x, y; asm("mov.b64 {%0, %1}, %2;" : "=r"(x), "=r"(y) : "l"(v));
    a = __int_as_float(x); b = __int_as_float(y);
}
__device__ __forceinline__ u64 fma2(u64 a, u64 b, u64 c) {
    u64 d; asm("fma.rn.f32x2 %0, %1, %2, %3;" : "=l"(d) : "l"(a), "l"(b), "l"(c)); return d;
}

// ---------- graph setup ----------
__device__ __forceinline__ int edge_src(const int* ei, int i, int w64) { return w64 ? ei[2 * i] : ei[i]; }
__device__ __forceinline__ int edge_dst(const int* ei, int i, int w64) { return w64 ? ei[2 * (NEDGES + i)] : ei[NEDGES + i]; }

__global__ void setup_kernel(const int* __restrict__ ei) {
    int i = blockIdx.x * blockDim.x + threadIdx.x;
    if (i < NNODES) g_deg[i] = 0;
    if (i < 8) g_acc[i] = 0.0f;
    if (blockIdx.x == 0 && threadIdx.x == 0) {
        int nz = 0;
        for (int k = 1; k < 128; k += 2) nz += (ei[k] != 0);
        g_idx64 = (nz == 0) ? 1 : 0;
    }
}
__global__ void deg_count_kernel(const int* __restrict__ ei) {
    int i = blockIdx.x * blockDim.x + threadIdx.x;
    int w64 = g_idx64;
    if (i < NEDGES) atomicAdd(&g_deg[edge_dst(ei, i, w64)], 1);
}
__global__ void dinv_scan_kernel() {
    __shared__ int sums[32];
    int tid = threadIdx.x, base = tid * 4;
    int v[4], s = 0;
#pragma unroll
    for (int i = 0; i < 4; i++) {
        v[i] = g_deg[base + i];
        g_dinv[base + i] = rsqrtf((float)v[i] + 1.0f);
        s += v[i];
    }
    int lane = tid & 31, wid = tid >> 5, ss = s;
#pragma unroll
    for (int o = 1; o < 32; o <<= 1) { int t = __shfl_up_sync(~0u, ss, o); if (lane >= o) ss += t; }
    if (lane == 31) sums[wid] = ss;
    __syncthreads();
    if (wid == 0) {
        int w = sums[lane];
#pragma unroll
        for (int o = 1; o < 32; o <<= 1) { int t = __shfl_up_sync(~0u, w, o); if (lane >= o) w += t; }
        sums[lane] = w;
    }
    __syncthreads();
    int run = ss - s + (wid > 0 ? sums[wid - 1] : 0);
#pragma unroll
    for (int i = 0; i < 4; i++) { g_rowptr[base + i] = run; g_cursor[base + i] = run; run += v[i]; }
    if (tid == 1023) g_rowptr[NNODES] = run;
}
__global__ void csr_fill_kernel(const int* __restrict__ ei) {
    int i = blockIdx.x * blockDim.x + threadIdx.x;
    if (i >= NEDGES) return;
    int w64 = g_idx64;
    int s = edge_src(ei, i, w64), d = edge_dst(ei, i, w64);
    int pos = atomicAdd(&g_cursor[d], 1);
    g_col[pos] = s;
    g_w[pos] = g_dinv[s] * g_dinv[d];
}

// ---------- SGEMM 64x128, BK=16, f32x2; DST=0: g_h1 f32, DST=1: g_he16 bf16 ----
template <int DST>
__global__ __launch_bounds__(256) void sgemm16(const float* __restrict__ A,
                                               const float* __restrict__ B,
                                               int K, float scale) {
    __shared__ float As[16][65];
    __shared__ float Bs[16][128];
    int tid = threadIdx.x;
    const float* Ab = A + (size_t)blockIdx.y * 64 * K;
    const float* Bb = B + blockIdx.x * 128;
    int aRow = tid >> 2, aCol = (tid & 3) * 4;
    int bRow = tid >> 5, bCol = (tid & 31) * 4;
    int ty = tid >> 4, tx = tid & 15;
    u64 acc2[4][4] = {};
    for (int k0 = 0; k0 < K; k0 += 16) {
        float4 a4 = *reinterpret_cast<const float4*>(Ab + (size_t)aRow * K + k0 + aCol);
        float4 b4a = *reinterpret_cast<const float4*>(Bb + (size_t)(k0 + bRow) * HID + bCol);
        float4 b4b = *reinterpret_cast<const float4*>(Bb + (size_t)(k0 + bRow + 8) * HID + bCol);
        __syncthreads();
        As[aCol + 0][aRow] = a4.x; As[aCol + 1][aRow] = a4.y;
        As[aCol + 2][aRow] = a4.z; As[aCol + 3][aRow] = a4.w;
        *reinterpret_cast<float4*>(&Bs[bRow][bCol]) = b4a;
        *reinterpret_cast<float4*>(&Bs[bRow + 8][bCol]) = b4b;
        __syncthreads();
#pragma unroll
        for (int kk = 0; kk < 16; kk++) {
            u64 b2[4];
#pragma unroll
            for (int p = 0; p < 4; p++) b2[p] = reinterpret_cast<const u64*>(&Bs[kk][tx * 8])[p];
#pragma unroll
            for (int i = 0; i < 4; i++) {
                float a = As[kk][ty * 4 + i];
                u64 a2 = pack2(a, a);
#pragma unroll
                for (int p = 0; p < 4; p++) acc2[i][p] = fma2(a2, b2[p], acc2[i][p]);
            }
        }
    }
#pragma unroll
    for (int i = 0; i < 4; i++) {
        size_t row = (size_t)blockIdx.y * 64 + ty * 4 + i;
        int col = blockIdx.x * 128 + tx * 8;
        float v[8];
#pragma unroll
        for (int p = 0; p < 4; p++) {
            float lo, hi; unpack2f(acc2[i][p], lo, hi);
            v[2 * p] = lo * scale; v[2 * p + 1] = hi * scale;
        }
        if (DST == 0) {
            float4 o0 = {v[0], v[1], v[2], v[3]}, o1 = {v[4], v[5], v[6], v[7]};
            *reinterpret_cast<float4*>(&g_h1[row * HID + col]) = o0;
            *reinterpret_cast<float4*>(&g_h1[row * HID + col + 4]) = o1;
        } else {
            __nv_bfloat162 h[4];
#pragma unroll
            for (int p = 0; p < 4; p++) h[p] = __floats2bfloat162_rn(v[2 * p], v[2 * p + 1]);
            *reinterpret_cast<uint4*>(&g_he16[row * HID + col]) = *reinterpret_cast<uint4*>(h);
        }
    }
}

// ---------- hx = relu(P(h1)+b1), fused sumsq ----------
__global__ __launch_bounds__(256) void prop256x_kernel(const float* __restrict__ bias) {
    int n = blockIdx.x, c = threadIdx.x;
    int start = g_rowptr[n], end = g_rowptr[n + 1];
    float d = g_dinv[n];
    float acc = g_h1[(size_t)n * HID + c] * d * d;
    for (int j = start; j < end; j++)
        acc = fmaf(g_w[j], g_h1[(size_t)g_col[j] * HID + c], acc);
    acc = fmaxf(acc + bias[c], 0.0f);
    g_hx[(size_t)n * HID + c] = acc;
    float s = acc * acc;
#pragma unroll
    for (int o = 16; o > 0; o >>= 1) s += __shfl_down_sync(~0u, s, o);
    __shared__ float ws[8];
    if ((c & 31) == 0) ws[c >> 5] = s;
    __syncthreads();
    if (c < 8) {
        s = ws[c];
#pragma unroll
        for (int o = 4; o > 0; o >>= 1) s += __shfl_down_sync(0xffu, s, o);
        if (c == 0) atomicAdd(&g_acc[0], s);
    }
}

// ---------- sumsq(P(he)+be) per batch, bf16 gathers, no store ----------
__global__ __launch_bounds__(128) void prop256e_kernel(const float* __restrict__ be) {
    int n = blockIdx.x, b = blockIdx.y, c2 = threadIdx.x;
    const __nv_bfloat162* hb =
        reinterpret_cast<const __nv_bfloat162*>(g_he16 + (size_t)b * NNODES * HID);
    int start = g_rowptr[n], end = g_rowptr[n + 1];
    float d = g_dinv[n];
    float2 self = __bfloat1622float2(hb[n * 128 + c2]);
    float ax = self.x * d * d, ay = self.y * d * d;
    for (int j = start; j < end; j++) {
        float w = g_w[j];
        float2 v = __bfloat1622float2(hb[g_col[j] * 128 + c2]);
        ax = fmaf(w, v.x, ax); ay = fmaf(w, v.y, ay);
    }
    ax += be[2 * c2]; ay += be[2 * c2 + 1];
    float s = ax * ax + ay * ay;
#pragma unroll
    for (int o = 16; o > 0; o >>= 1) s += __shfl_down_sync(~0u, s, o);
    __shared__ float ws[4];
    if ((c2 & 31) == 0) ws[c2 >> 5] = s;
    __syncthreads();
    if (c2 == 0) atomicAdd(&g_acc[1 + b], ws[0] + ws[1] + ws[2] + ws[3]);
}

// ---------- we32 = We@[Wmu|Wsig] (blocks 0-7) + bewc = be@[Wmu|Wsig] (block 8) --
__global__ void wproj_kernel(const float* __restrict__ We, const float* __restrict__ be,
                             const float* __restrict__ Wmu, const float* __restrict__ Wsig) {
    if (blockIdx.x < 8) {
        int idx = blockIdx.x * 256 + threadIdx.x;
        int i = idx >> 5, j = idx & 31;
        const float* W = (j < 16) ? Wmu : Wsig;
        int jj = j & 15;
        float acc = 0.0f;
#pragma unroll 8
        for (int k = 0; k < HID; k++) acc = fmaf(We[i * HID + k], W[k * 16 + jj], acc);
        g_we32[i * 32 + j] = acc;
    } else if (threadIdx.x < 32) {
        int j = threadIdx.x;
        const float* W = (j < 16) ? Wmu : Wsig;
        int jj = j & 15;
        float acc = 0.0f;
        for (int k = 0; k < HID; k++) acc = fmaf(be[k], W[k * 16 + jj], acc);
        g_bewc[j] = acc;
    }
}
// ---------- the = R*e@we32 (blocks<2560) | thx = hx@[Wmu|Wsig] (blocks>=2560) ---
__global__ __launch_bounds__(256) void midproj_kernel(const float* __restrict__ e_noise,
                                                      const float* __restrict__ Wmu,
                                                      const float* __restrict__ Wsig) {
    int tid = threadIdx.x;
    int lr = tid >> 5, c = tid & 31;
    if (blockIdx.x < 2560) {
        __shared__ float se[8][64];
        __shared__ float sw[64 * 32];
        int r0 = blockIdx.x * 8;
        for (int i = tid; i < 512; i += 256)
            se[i >> 6][i & 63] = e_noise[(size_t)(r0 + (i >> 6)) * 64 + (i & 63)] * REWEIGHT;
        for (int i = tid; i < 2048; i += 256) sw[i] = g_we32[i];
        __syncthreads();
        float acc = 0.0f;
#pragma unroll 8
        for (int k = 0; k < 64; k++) acc = fmaf(se[lr][k], sw[k * 32 + c], acc);
        g_the[(size_t)(r0 + lr) * 32 + c] = acc;
    } else {
        __shared__ float s[8 * 256];
        int r0 = (blockIdx.x - 2560) * 8;
        for (int i = tid; i < 2048; i += 256) s[i] = g_hx[(size_t)r0 * HID + i];
        __syncthreads();
        const float* W = (c < 16) ? Wmu : Wsig;
        int cc = c & 15;
        float acc = 0.0f;
        const float* srow = &s[lr * 256];
#pragma unroll 8
        for (int k = 0; k < 256; k++) acc = fmaf(srow[k], W[k * 16 + cc], acc);
        g_thx[(size_t)(r0 + lr) * 32 + c] = acc;
    }
}
// ---------- t = thx + P(the) + bewc ----------
__global__ void tmid_kernel() {
    int warp = (blockIdx.x * blockDim.x + threadIdx.x) >> 5;
    int lane = threadIdx.x & 31;
    int b = warp >> 12, n = warp & (NNODES - 1);
    const float* tb = g_the + (size_t)b * NNODES * 32;
    float d = g_dinv[n];
    float acc = tb[(size_t)n * 32 + lane] * d * d;
    int start = g_rowptr[n], end = g_rowptr[n + 1];
    for (int j = start; j < end; j++)
        acc = fmaf(g_w[j], tb[(size_t)g_col[j] * 32 + lane], acc);
    g_t[(size_t)warp * 32 + lane] = acc + g_thx[(size_t)n * 32 + lane] + g_bewc[lane];
}
// ---------- mu/sig = P(t) + bias ----------
__global__ void prop32_kernel(const float* __restrict__ bmu, const float* __restrict__ bsig,
                              float* __restrict__ out) {
    int warp = (blockIdx.x * blockDim.x + threadIdx.x) >> 5;
    int lane = threadIdx.x & 31;
    int b = warp >> 12, n = warp & (NNODES - 1);
    const float* tb = g_t + (size_t)b * NNODES * 32;
    float d = g_dinv[n];
    float acc = tb[(size_t)n * 32 + lane] * d * d;
    int start = g_rowptr[n], end = g_rowptr[n + 1];
    for (int j = start; j < end; j++)
        acc = fmaf(g_w[j], tb[(size_t)g_col[j] * 32 + lane], acc);
    size_t base = ((size_t)b * NNODES + n) * OUTD;
    if (lane < 16) out[OFF_MU + base + lane] = acc + bmu[lane];
    else           out[OFF_SIG + base + (lane - 16)] = acc + bsig[lane - 16];
}

// ---------- z + finalize ----------
__global__ void zfin_kernel(const float* __restrict__ eps, const float* __restrict__ rk_lgt,
                            float* __restrict__ out) {
    int i = blockIdx.x * blockDim.x + threadIdx.x;
    int b = i / (NNODES * OUTD);
    int rem = i - b * (NNODES * OUTD);
    size_t src = (size_t)(b + 2) * NNODES * OUTD + rem;
    float zv = fmaf(eps[i], __expf(0.5f * out[OFF_SIG + src]), out[OFF_MU + src]);
    out[OFF_Z + i] = zv;
    out[OFF_ZS + i] = zv;
    out[OFF_EPS + i] = eps[i];
    if (blockIdx.x == 0 && threadIdx.x < 32) {
        int t = threadIdx.x;
        if (t < 5) out[OFF_SNR + t] = g_acc[0] / g_acc[1 + t];
        if (t < 16) out[OFF_RK + t] = sqrtf(1.0f / (1.0f + expf(-rk_lgt[t])));
    }
}

// ---------- adj = sigmoid(z z^T): 128x128 tile, MUFU sigmoid ----------
__device__ __forceinline__ float sigmoid1(float x) {
    float e = __expf(-x);
    float d = 1.0f + e;
    float r; asm("rcp.approx.f32 %0, %1;" : "=f"(r) : "f"(d));
    return r;
}

__global__ __launch_bounds__(256) void adj_kernel(float* __restrict__ out) {
    const float* zb = out + OFF_Z + (size_t)blockIdx.z * NNODES * OUTD;
    float* ab = out + OFF_ADJ + (size_t)blockIdx.z * NNODES * NNODES;
    __shared__ float ziT[16][132];
    __shared__ float zjT[16][132];
    int i0 = blockIdx.y * 128, j0 = blockIdx.x * 128;
    int tid = threadIdx.x;
#pragma unroll
    for (int rnd = 0; rnd < 2; rnd++) {
        int L4 = tid + rnd * 256;
        float4 a = *reinterpret_cast<const float4*>(zb + (size_t)i0 * 16 + L4 * 4);
        float4 b = *reinterpret_cast<const float4*>(zb + (size_t)j0 * 16 + L4 * 4);
        int r = L4 >> 2, k0 = (L4 & 3) * 4;
        ziT[k0 + 0][r] = a.x; ziT[k0 + 1][r] = a.y; ziT[k0 + 2][r] = a.z; ziT[k0 + 3][r] = a.w;
        zjT[k0 + 0][r] = b.x; zjT[k0 + 1][r] = b.y; zjT[k0 + 2][r] = b.z; zjT[k0 + 3][r] = b.w;
    }
    __syncthreads();
    int tx = tid & 15, ty = tid >> 4;
    u64 acc2[8][4] = {};
#pragma unroll
    for (int k = 0; k < 16; k++) {
        float4 b0 = *reinterpret_cast<const float4*>(&zjT[k][tx * 8]);
        float4 b1 = *reinterpret_cast<const float4*>(&zjT[k][tx * 8 + 4]);
        u64 b2[4];
        b2[0] = pack2(b0.x, b0.y); b2[1] = pack2(b0.z, b0.w);
        b2[2] = pack2(b1.x, b1.y); b2[3] = pack2(b1.z, b1.w);
        float4 a0 = *reinterpret_cast<const float4*>(&ziT[k][ty * 8]);
        float4 a1 = *reinterpret_cast<const float4*>(&ziT[k][ty * 8 + 4]);
        float av[8] = {a0.x, a0.y, a0.z, a0.w, a1.x, a1.y, a1.z, a1.w};
#pragma unroll
        for (int i = 0; i < 8; i++) {
            u64 a2 = pack2(av[i], av[i]);
#pragma unroll
            for (int p = 0; p < 4; p++) acc2[i][p] = fma2(a2, b2[p], acc2[i][p]);
        }
    }
#pragma unroll
    for (int i = 0; i < 8; i++) {
        float v[8];
#pragma unroll
        for (int p = 0; p < 4; p++) unpack2f(acc2[i][p], v[2 * p], v[2 * p + 1]);
        float4 o0, o1;
        o0.x = sigmoid1(v[0]); o0.y = sigmoid1(v[1]); o0.z = sigmoid1(v[2]); o0.w = sigmoid1(v[3]);
        o1.x = sigmoid1(v[4]); o1.y = sigmoid1(v[5]); o1.z = sigmoid1(v[6]); o1.w = sigmoid1(v[7]);
        float* row = ab + (size_t)(i0 + ty * 8 + i) * NNODES + j0 + tx * 8;
        *reinterpret_cast<float4*>(row) = o0;
        *reinterpret_cast<float4*>(row + 4) = o1;
    }
}

// =================================================================================
extern "C" void kernel_launch(void* const* d_in, const int* in_sizes, int n_in,
                              void* d_out, int out_size) {
    (void)in_sizes; (void)n_in; (void)out_size;
    const float* x       = (const float*)d_in[0];
    const int*   ei      = (const int*)d_in[1];
    const float* e_noise = (const float*)d_in[2];
    const float* eps     = (const float*)d_in[3];
    const float* W1      = (const float*)d_in[4];
    const float* b1      = (const float*)d_in[5];
    const float* We      = (const float*)d_in[6];
    const float* be      = (const float*)d_in[7];
    const float* Wmu     = (const float*)d_in[8];
    const float* bmu     = (const float*)d_in[9];
    const float* Wsig    = (const float*)d_in[10];
    const float* bsig    = (const float*)d_in[11];
    const float* rk_lgt  = (const float*)d_in[12];
    float* out = (float*)d_out;

    // one-time stream/event handles (host resources, not device memory)
    static cudaStream_t s1 = nullptr, s2 = nullptr;
    static cudaEvent_t ev_root, ev_csr, ev_w2, ev_e;
    if (!s1) {
        cudaStreamCreateWithFlags(&s1, cudaStreamNonBlocking);
        cudaStreamCreateWithFlags(&s2, cudaStreamNonBlocking);
        cudaEventCreateWithFlags(&ev_root, cudaEventDisableTiming);
        cudaEventCreateWithFlags(&ev_csr, cudaEventDisableTiming);
        cudaEventCreateWithFlags(&ev_w2, cudaEventDisableTiming);
        cudaEventCreateWithFlags(&ev_e, cudaEventDisableTiming);
    }

    // fork
    cudaEventRecord(ev_root, 0);
    cudaStreamWaitEvent(s1, ev_root, 0);
    cudaStreamWaitEvent(s2, ev_root, 0);

    // s1: e-feature GEMM immediately (independent of graph)
    sgemm16<1><<<dim3(2, NB_E * NNODES / 64), 256, 0, s1>>>(e_noise, We, E_CH, REWEIGHT);

    // s2: weight projection + x-feature GEMM (independent of graph)
    wproj_kernel<<<9, 256, 0, s2>>>(We, be, Wmu, Wsig);
    sgemm16<0><<<dim3(2, NNODES / 64), 256, 0, s2>>>(x, W1, IN_CH, 1.0f);
    cudaEventRecord(ev_w2, s2);

    // s0: graph setup
    setup_kernel<<<16, 256>>>(ei);
    deg_count_kernel<<<NEDGES / 256, 256>>>(ei);
    dinv_scan_kernel<<<1, 1024>>>();
    csr_fill_kernel<<<NEDGES / 256, 256>>>(ei);
    cudaEventRecord(ev_csr, 0);

    // s1: noise-propagation sumsq (needs CSR + sgemm1), off critical path
    cudaStreamWaitEvent(s1, ev_csr, 0);
    prop256e_kernel<<<dim3(NNODES, NB_E), 128, 0, s1>>>(be);
    cudaEventRecord(ev_e, s1);

    // s0: critical path
    cudaStreamWaitEvent(0, ev_w2, 0);
    prop256x_kernel<<<NNODES, 256>>>(b1);
    midproj_kernel<<<2560 + 512, 256>>>(e_noise, Wmu, Wsig);
    tmid_kernel<<<2560, 256>>>();
    prop32_kernel<<<2560, 256>>>(bmu, bsig, out);
    cudaStreamWaitEvent(0, ev_e, 0);   // snr needs g_acc
    zfin_kernel<<<NB_Z * NNODES * OUTD / 256, 256>>>(eps, rk_lgt, out);
    adj_kernel<<<dim3(32, 32, NB_Z), 256>>>(out);
}

// round 9
// speedup vs baseline: 1.1272x; 1.1272x over previous
#include <cuda_runtime.h>
#include <cuda_bf16.h>
#include <cstdint>

#define NNODES 4096
#define NEDGES 131072
#define IN_CH 512
#define E_CH 64
#define HID 256
#define OUTD 16
#define NB_E 5
#define NB_Z 3
#define REWEIGHT 0.6454972243679028f

typedef unsigned long long u64;

__device__ int   g_deg[NNODES];          // zeroed statically; re-zeroed by phase3 each call
__device__ int   g_rowptr[NNODES + 1];
__device__ int   g_cursor[NNODES];
__device__ float g_dinv[NNODES];
__device__ int   g_col[NEDGES];
__device__ float g_w[NEDGES];
__device__ float g_h1[NNODES * HID];
__device__ float g_hx[NNODES * HID];
__device__ __nv_bfloat16 g_he16[NB_E * NNODES * HID];
__device__ float g_we32[E_CH * 32];
__device__ float g_bewc[32];
__device__ float g_the[NB_E * NNODES * 32];
__device__ float g_thx[NNODES * 32];
__device__ float g_t[NB_E * NNODES * 32];
__device__ float g_acc[8];

#define OFF_ADJ 0ull
#define OFF_MU  (OFF_ADJ + 3ull * NNODES * NNODES)
#define OFF_SIG (OFF_MU  + (u64)NB_E * NNODES * OUTD)
#define OFF_Z   (OFF_SIG + (u64)NB_E * NNODES * OUTD)
#define OFF_ZS  (OFF_Z   + (u64)NB_Z * NNODES * OUTD)
#define OFF_EPS (OFF_ZS  + (u64)NB_Z * NNODES * OUTD)
#define OFF_RK  (OFF_EPS + (u64)NB_Z * NNODES * OUTD)
#define OFF_SNR (OFF_RK + 16ull)

// ---------- f32x2 helpers ----------
__device__ __forceinline__ u64 pack2(float a, float b) {
    u64 r; asm("mov.b64 %0, {%1, %2};" : "=l"(r) : "r"(__float_as_int(a)), "r"(__float_as_int(b))); return r;
}
__device__ __forceinline__ void unpack2f(u64 v, float& a, float& b) {
    int x, y; asm("mov.b64 {%0, %1}, %2;" : "=r"(x), "=r"(y) : "l"(v));
    a = __int_as_float(x); b = __int_as_float(y);
}
__device__ __forceinline__ u64 fma2(u64 a, u64 b, u64 c) {
    u64 d; asm("fma.rn.f32x2 %0, %1, %2, %3;" : "=l"(d) : "l"(a), "l"(b), "l"(c)); return d;
}

// ---------- edge access with inline int64 detection ----------
__device__ __forceinline__ int detect_w64(const int* __restrict__ ei) {
    return (ei[1] | ei[3] | ei[5] | ei[7] | ei[9] | ei[11] | ei[13] | ei[15]) == 0;
}
__device__ __forceinline__ int edge_src(const int* ei, int i, int w64) { return w64 ? ei[2 * i] : ei[i]; }
__device__ __forceinline__ int edge_dst(const int* ei, int i, int w64) { return w64 ? ei[2 * (NEDGES + i)] : ei[NEDGES + i]; }

// ---------- sgemm body (64x128 tile, BK=16, f32x2) ----------
template <int DST>
__device__ __forceinline__ void sgemm_body(const float* __restrict__ A, const float* __restrict__ B,
                                           int K, float scale, int bxx, int by, float* pool) {
    float (*As)[65]  = reinterpret_cast<float(*)[65]>(pool);
    float (*Bs)[128] = reinterpret_cast<float(*)[128]>(pool + 16 * 65);
    int tid = threadIdx.x;
    const float* Ab = A + (size_t)by * 64 * K;
    const float* Bb = B + bxx * 128;
    int aRow = tid >> 2, aCol = (tid & 3) * 4;
    int bRow = tid >> 5, bCol = (tid & 31) * 4;
    int ty = tid >> 4, tx = tid & 15;
    u64 acc2[4][4] = {};
    for (int k0 = 0; k0 < K; k0 += 16) {
        float4 a4 = *reinterpret_cast<const float4*>(Ab + (size_t)aRow * K + k0 + aCol);
        float4 b4a = *reinterpret_cast<const float4*>(Bb + (size_t)(k0 + bRow) * HID + bCol);
        float4 b4b = *reinterpret_cast<const float4*>(Bb + (size_t)(k0 + bRow + 8) * HID + bCol);
        __syncthreads();
        As[aCol + 0][aRow] = a4.x; As[aCol + 1][aRow] = a4.y;
        As[aCol + 2][aRow] = a4.z; As[aCol + 3][aRow] = a4.w;
        *reinterpret_cast<float4*>(&Bs[bRow][bCol]) = b4a;
        *reinterpret_cast<float4*>(&Bs[bRow + 8][bCol]) = b4b;
        __syncthreads();
#pragma unroll
        for (int kk = 0; kk < 16; kk++) {
            u64 b2[4];
#pragma unroll
            for (int p = 0; p < 4; p++) b2[p] = reinterpret_cast<const u64*>(&Bs[kk][tx * 8])[p];
#pragma unroll
            for (int i = 0; i < 4; i++) {
                float a = As[kk][ty * 4 + i];
                u64 a2 = pack2(a, a);
#pragma unroll
                for (int p = 0; p < 4; p++) acc2[i][p] = fma2(a2, b2[p], acc2[i][p]);
            }
        }
    }
#pragma unroll
    for (int i = 0; i < 4; i++) {
        size_t row = (size_t)by * 64 + ty * 4 + i;
        int col = bxx * 128 + tx * 8;
        float v[8];
#pragma unroll
        for (int p = 0; p < 4; p++) {
            float lo, hi; unpack2f(acc2[i][p], lo, hi);
            v[2 * p] = lo * scale; v[2 * p + 1] = hi * scale;
        }
        if (DST == 0) {
            float4 o0 = {v[0], v[1], v[2], v[3]}, o1 = {v[4], v[5], v[6], v[7]};
            *reinterpret_cast<float4*>(&g_h1[row * HID + col]) = o0;
            *reinterpret_cast<float4*>(&g_h1[row * HID + col + 4]) = o1;
        } else {
            __nv_bfloat162 h[4];
#pragma unroll
            for (int p = 0; p < 4; p++) h[p] = __floats2bfloat162_rn(v[2 * p], v[2 * p + 1]);
            *reinterpret_cast<uint4*>(&g_he16[row * HID + col]) = *reinterpret_cast<uint4*>(h);
        }
    }
}

// ========== K1: deg_count | wproj | sgemm0 | sgemm1 ==========
__global__ __launch_bounds__(256) void phase1_kernel(const int* __restrict__ ei,
                                                     const float* __restrict__ x,
                                                     const float* __restrict__ W1,
                                                     const float* __restrict__ e_noise,
                                                     const float* __restrict__ We,
                                                     const float* __restrict__ be,
                                                     const float* __restrict__ Wmu,
                                                     const float* __restrict__ Wsig) {
    __shared__ float pool[16 * 65 + 16 * 128];
    int bx = blockIdx.x, tid = threadIdx.x;
    if (bx < 512) {
        int w64 = detect_w64(ei);
        int i = bx * 256 + tid;
        atomicAdd(&g_deg[edge_dst(ei, i, w64)], 1);
    } else if (bx < 521) {
        int b = bx - 512;
        if (b < 8) {
            int idx = b * 256 + tid;
            int i = idx >> 5, j = idx & 31;
            const float* W = (j < 16) ? Wmu : Wsig;
            int jj = j & 15;
            float acc = 0.0f;
#pragma unroll 8
            for (int k = 0; k < HID; k++) acc = fmaf(We[i * HID + k], W[k * 16 + jj], acc);
            g_we32[i * 32 + j] = acc;
        } else if (tid < 32) {
            const float* W = (tid < 16) ? Wmu : Wsig;
            int jj = tid & 15;
            float acc = 0.0f;
            for (int k = 0; k < HID; k++) acc = fmaf(be[k], W[k * 16 + jj], acc);
            g_bewc[tid] = acc;
        }
    } else if (bx < 649) {
        int bid = bx - 521;
        sgemm_body<0>(x, W1, IN_CH, 1.0f, bid & 1, bid >> 1, pool);
    } else {
        int bid = bx - 649;
        sgemm_body<1>(e_noise, We, E_CH, REWEIGHT, bid & 1, bid >> 1, pool);
    }
}

// ========== K2: dinv + scan + g_acc zero ==========
__global__ void dinv_scan_kernel() {
    __shared__ int sums[32];
    int tid = threadIdx.x, base = tid * 4;
    if (tid < 8) g_acc[tid] = 0.0f;
    int v[4], s = 0;
#pragma unroll
    for (int i = 0; i < 4; i++) {
        v[i] = g_deg[base + i];
        g_dinv[base + i] = rsqrtf((float)v[i] + 1.0f);
        s += v[i];
    }
    int lane = tid & 31, wid = tid >> 5, ss = s;
#pragma unroll
    for (int o = 1; o < 32; o <<= 1) { int t = __shfl_up_sync(~0u, ss, o); if (lane >= o) ss += t; }
    if (lane == 31) sums[wid] = ss;
    __syncthreads();
    if (wid == 0) {
        int w = sums[lane];
#pragma unroll
        for (int o = 1; o < 32; o <<= 1) { int t = __shfl_up_sync(~0u, w, o); if (lane >= o) w += t; }
        sums[lane] = w;
    }
    __syncthreads();
    int run = ss - s + (wid > 0 ? sums[wid - 1] : 0);
#pragma unroll
    for (int i = 0; i < 4; i++) { g_rowptr[base + i] = run; g_cursor[base + i] = run; run += v[i]; }
    if (tid == 1023) g_rowptr[NNODES] = run;
}

// ========== K3: csr_fill (+deg re-zero) | the-projection ==========
__global__ __launch_bounds__(256) void phase3_kernel(const int* __restrict__ ei,
                                                     const float* __restrict__ e_noise) {
    __shared__ float pool[2560];
    int bx = blockIdx.x, tid = threadIdx.x;
    if (bx < 512) {
        int w64 = detect_w64(ei);
        int i = bx * 256 + tid;
        int s = edge_src(ei, i, w64), d = edge_dst(ei, i, w64);
        int pos = atomicAdd(&g_cursor[d], 1);
        g_col[pos] = s;
        g_w[pos] = g_dinv[s] * g_dinv[d];
        if (i < NNODES) g_deg[i] = 0;   // reset for next graph replay
    } else {
        float (*se)[64] = reinterpret_cast<float(*)[64]>(pool);
        float* sw = pool + 512;
        int r0 = (bx - 512) * 8;
        for (int i = tid; i < 512; i += 256)
            se[i >> 6][i & 63] = e_noise[(size_t)(r0 + (i >> 6)) * 64 + (i & 63)] * REWEIGHT;
        for (int i = tid; i < 2048; i += 256) sw[i] = g_we32[i];
        __syncthreads();
        int lr = tid >> 5, c = tid & 31;
        float acc = 0.0f;
#pragma unroll 8
        for (int k = 0; k < 64; k++) acc = fmaf(se[lr][k], sw[k * 32 + c], acc);
        g_the[(size_t)(r0 + lr) * 32 + c] = acc;
    }
}

// ========== K4: prop256x(+thx,+sumsq) | prop256e(sumsq) ==========
__global__ __launch_bounds__(256) void phase4_kernel(const float* __restrict__ b1,
                                                     const float* __restrict__ be,
                                                     const float* __restrict__ Wmu,
                                                     const float* __restrict__ Wsig) {
    __shared__ float sh[256];
    __shared__ float red[8][32];
    __shared__ float ws[8];
    int bx = blockIdx.x, tid = threadIdx.x;
    if (bx < NNODES) {
        int n = bx, c = tid;
        int start = g_rowptr[n], end = g_rowptr[n + 1];
        float d = g_dinv[n];
        float acc = g_h1[(size_t)n * HID + c] * d * d;
        for (int j = start; j < end; j++)
            acc = fmaf(g_w[j], g_h1[(size_t)g_col[j] * HID + c], acc);
        acc = fmaxf(acc + b1[c], 0.0f);
        g_hx[(size_t)n * HID + c] = acc;
        sh[c] = acc;
        float s = acc * acc;
#pragma unroll
        for (int o = 16; o > 0; o >>= 1) s += __shfl_down_sync(~0u, s, o);
        if ((c & 31) == 0) ws[c >> 5] = s;
        __syncthreads();
        if (c < 8) {
            s = ws[c];
#pragma unroll
            for (int o = 4; o > 0; o >>= 1) s += __shfl_down_sync(0xffu, s, o);
            if (c == 0) atomicAdd(&g_acc[0], s);
        }
        // thx = hx_row @ [Wmu|Wsig]
        int c0 = tid & 31, seg = tid >> 5;
        const float* W = (c0 < 16) ? Wmu : Wsig;
        int cc = c0 & 15;
        float t = 0.0f;
        int k0 = seg * 32;
#pragma unroll 8
        for (int k = k0; k < k0 + 32; k++) t = fmaf(sh[k], W[k * 16 + cc], t);
        red[seg][c0] = t;
        __syncthreads();
        if (tid < 32) {
            float t2 = 0.0f;
#pragma unroll
            for (int g = 0; g < 8; g++) t2 += red[g][tid];
            g_thx[(size_t)n * 32 + tid] = t2;
        }
    } else {
        int bid = bx - NNODES;               // [0, 10240)
        int b = bid >> 11;                   // batch
        int n = ((bid & 2047) << 1) + (tid >> 7);
        int c2 = tid & 127;
        const __nv_bfloat162* hb =
            reinterpret_cast<const __nv_bfloat162*>(g_he16 + (size_t)b * NNODES * HID);
        int start = g_rowptr[n], end = g_rowptr[n + 1];
        float d = g_dinv[n];
        float2 self = __bfloat1622float2(hb[n * 128 + c2]);
        float ax = self.x * d * d, ay = self.y * d * d;
        for (int j = start; j < end; j++) {
            float w = g_w[j];
            float2 v = __bfloat1622float2(hb[g_col[j] * 128 + c2]);
            ax = fmaf(w, v.x, ax); ay = fmaf(w, v.y, ay);
        }
        ax += be[2 * c2]; ay += be[2 * c2 + 1];
        float s = ax * ax + ay * ay;
#pragma unroll
        for (int o = 16; o > 0; o >>= 1) s += __shfl_down_sync(~0u, s, o);
        if ((tid & 31) == 0) ws[tid >> 5] = s;
        __syncthreads();
        if ((tid & 127) == 0) {
            int base = (tid >> 7) * 4;
            atomicAdd(&g_acc[1 + b], ws[base] + ws[base + 1] + ws[base + 2] + ws[base + 3]);
        }
    }
}

// ========== K5: t = thx + P(the) + bewc ==========
__global__ void tmid_kernel() {
    int warp = (blockIdx.x * blockDim.x + threadIdx.x) >> 5;
    int lane = threadIdx.x & 31;
    int b = warp >> 12, n = warp & (NNODES - 1);
    const float* tb = g_the + (size_t)b * NNODES * 32;
    float d = g_dinv[n];
    float acc = tb[(size_t)n * 32 + lane] * d * d;
    int start = g_rowptr[n], end = g_rowptr[n + 1];
    for (int j = start; j < end; j++)
        acc = fmaf(g_w[j], tb[(size_t)g_col[j] * 32 + lane], acc);
    g_t[(size_t)warp * 32 + lane] = acc + g_thx[(size_t)n * 32 + lane] + g_bewc[lane];
}

// ========== K6: mu/sig = P(t) + bias, fused z ==========
__global__ void prop32z_kernel(const float* __restrict__ bmu, const float* __restrict__ bsig,
                               const float* __restrict__ eps, float* __restrict__ out) {
    int warp = (blockIdx.x * blockDim.x + threadIdx.x) >> 5;
    int lane = threadIdx.x & 31;
    int b = warp >> 12, n = warp & (NNODES - 1);
    const float* tb = g_t + (size_t)b * NNODES * 32;
    float d = g_dinv[n];
    float acc = tb[(size_t)n * 32 + lane] * d * d;
    int start = g_rowptr[n], end = g_rowptr[n + 1];
    for (int j = start; j < end; j++)
        acc = fmaf(g_w[j], tb[(size_t)g_col[j] * 32 + lane], acc);
    float biased = acc + ((lane < 16) ? bmu[lane] : bsig[lane - 16]);
    size_t base = ((size_t)b * NNODES + n) * OUTD;
    if (lane < 16) out[OFF_MU + base + lane] = biased;
    else           out[OFF_SIG + base + (lane - 16)] = biased;
    if (b >= 2) {
        float sig = __shfl_sync(~0u, biased, lane + 16);
        if (lane < 16) {
            size_t zi = ((size_t)(b - 2) * NNODES + n) * OUTD + lane;
            float e = eps[zi];
            float zv = fmaf(e, __expf(0.5f * sig), biased);
            out[OFF_Z + zi] = zv;
            out[OFF_ZS + zi] = zv;
            out[OFF_EPS + zi] = e;
        }
    }
}

// ========== K7: adj = sigmoid(z z^T) + snr/rk tail ==========
__device__ __forceinline__ float sigmoid1(float x) {
    float e = __expf(-x);
    float d = 1.0f + e;
    float r; asm("rcp.approx.f32 %0, %1;" : "=f"(r) : "f"(d));
    return r;
}

__global__ __launch_bounds__(256) void adj_kernel(const float* __restrict__ rk_lgt,
                                                  float* __restrict__ out) {
    int tid = threadIdx.x;
    if (blockIdx.x == 0 && blockIdx.y == 0 && blockIdx.z == 0 && tid < 32) {
        if (tid < 5) out[OFF_SNR + tid] = g_acc[0] / g_acc[1 + tid];
        if (tid < 16) out[OFF_RK + tid] = sqrtf(1.0f / (1.0f + expf(-rk_lgt[tid])));
    }
    const float* zb = out + OFF_Z + (size_t)blockIdx.z * NNODES * OUTD;
    float* ab = out + OFF_ADJ + (size_t)blockIdx.z * NNODES * NNODES;
    __shared__ float ziT[16][132];
    __shared__ float zjT[16][132];
    int i0 = blockIdx.y * 128, j0 = blockIdx.x * 128;
#pragma unroll
    for (int rnd = 0; rnd < 2; rnd++) {
        int L4 = tid + rnd * 256;
        float4 a = *reinterpret_cast<const float4*>(zb + (size_t)i0 * 16 + L4 * 4);
        float4 b = *reinterpret_cast<const float4*>(zb + (size_t)j0 * 16 + L4 * 4);
        int r = L4 >> 2, k0 = (L4 & 3) * 4;
        ziT[k0 + 0][r] = a.x; ziT[k0 + 1][r] = a.y; ziT[k0 + 2][r] = a.z; ziT[k0 + 3][r] = a.w;
        zjT[k0 + 0][r] = b.x; zjT[k0 + 1][r] = b.y; zjT[k0 + 2][r] = b.z; zjT[k0 + 3][r] = b.w;
    }
    __syncthreads();
    int tx = tid & 15, ty = tid >> 4;
    u64 acc2[8][4] = {};
#pragma unroll
    for (int k = 0; k < 16; k++) {
        float4 b0 = *reinterpret_cast<const float4*>(&zjT[k][tx * 8]);
        float4 b1 = *reinterpret_cast<const float4*>(&zjT[k][tx * 8 + 4]);
        u64 b2[4];
        b2[0] = pack2(b0.x, b0.y); b2[1] = pack2(b0.z, b0.w);
        b2[2] = pack2(b1.x, b1.y); b2[3] = pack2(b1.z, b1.w);
        float4 a0 = *reinterpret_cast<const float4*>(&ziT[k][ty * 8]);
        float4 a1 = *reinterpret_cast<const float4*>(&ziT[k][ty * 8 + 4]);
        float av[8] = {a0.x, a0.y, a0.z, a0.w, a1.x, a1.y, a1.z, a1.w};
#pragma unroll
        for (int i = 0; i < 8; i++) {
            u64 a2 = pack2(av[i], av[i]);
#pragma unroll
            for (int p = 0; p < 4; p++) acc2[i][p] = fma2(a2, b2[p], acc2[i][p]);
        }
    }
#pragma unroll
    for (int i = 0; i < 8; i++) {
        float v[8];
#pragma unroll
        for (int p = 0; p < 4; p++) unpack2f(acc2[i][p], v[2 * p], v[2 * p + 1]);
        float4 o0, o1;
        o0.x = sigmoid1(v[0]); o0.y = sigmoid1(v[1]); o0.z = sigmoid1(v[2]); o0.w = sigmoid1(v[3]);
        o1.x = sigmoid1(v[4]); o1.y = sigmoid1(v[5]); o1.z = sigmoid1(v[6]); o1.w = sigmoid1(v[7]);
        float* row = ab + (size_t)(i0 + ty * 8 + i) * NNODES + j0 + tx * 8;
        *reinterpret_cast<float4*>(row) = o0;
        *reinterpret_cast<float4*>(row + 4) = o1;
    }
}

// =================================================================================
extern "C" void kernel_launch(void* const* d_in, const int* in_sizes, int n_in,
                              void* d_out, int out_size) {
    (void)in_sizes; (void)n_in; (void)out_size;
    const float* x       = (const float*)d_in[0];
    const int*   ei      = (const int*)d_in[1];
    const float* e_noise = (const float*)d_in[2];
    const float* eps     = (const float*)d_in[3];
    const float* W1      = (const float*)d_in[4];
    const float* b1      = (const float*)d_in[5];
    const float* We      = (const float*)d_in[6];
    const float* be      = (const float*)d_in[7];
    const float* Wmu     = (const float*)d_in[8];
    const float* bmu     = (const float*)d_in[9];
    const float* Wsig    = (const float*)d_in[10];
    const float* bsig    = (const float*)d_in[11];
    const float* rk_lgt  = (const float*)d_in[12];
    float* out = (float*)d_out;

    phase1_kernel<<<512 + 9 + 128 + 640, 256>>>(ei, x, W1, e_noise, We, be, Wmu, Wsig);
    dinv_scan_kernel<<<1, 1024>>>();
    phase3_kernel<<<512 + 2560, 256>>>(ei, e_noise);
    phase4_kernel<<<NNODES + 10240, 256>>>(b1, be, Wmu, Wsig);
    tmid_kernel<<<2560, 256>>>();
    prop32z_kernel<<<2560, 256>>>(bmu, bsig, eps, out);
    adj_kernel<<<dim3(32, 32, NB_Z), 256>>>(rk_lgt, out);
}

// round 10
// speedup vs baseline: 1.4148x; 1.2551x over previous
#include <cuda_runtime.h>
#include <cstdint>

#define NNODES 4096
#define NEDGES 131072
#define IN_CH 512
#define E_CH 64
#define HID 256
#define OUTD 16
#define NB_E 5
#define NB_Z 3
#define REWEIGHT 0.6454972243679028f

typedef unsigned long long u64;

__device__ int   g_deg[NNODES];
__device__ int   g_rowptr[NNODES + 1];
__device__ int   g_cursor[NNODES];
__device__ float g_dinv[NNODES];
__device__ int2  g_cw[NEDGES];               // {col, float_bits(w)}
__device__ float g_h1[NNODES * HID];
__device__ float g_hx[NNODES * HID];
__device__ float g_we32[E_CH * 32];          // R * We @ [Wmu|Wsig]
__device__ float g_bewc[32];                 // be @ [Wmu|Wsig]
__device__ float g_G[E_CH * E_CH];           // R^2 * We We^T
__device__ float g_v[E_CH];                  // 2R * We @ be
__device__ float g_s0;                       // ||be||^2
__device__ float g_the[NB_E * NNODES * 32];  // R * (P e_noise) @ we32  (post-prop)
__device__ float g_thx[NNODES * 32];         // hx @ [Wmu|Wsig]
__device__ float g_t[NB_E * NNODES * 32];
__device__ float g_acc[8];

#define OFF_ADJ 0ull
#define OFF_MU  (OFF_ADJ + 3ull * NNODES * NNODES)
#define OFF_SIG (OFF_MU  + (u64)NB_E * NNODES * OUTD)
#define OFF_Z   (OFF_SIG + (u64)NB_E * NNODES * OUTD)
#define OFF_ZS  (OFF_Z   + (u64)NB_Z * NNODES * OUTD)
#define OFF_EPS (OFF_ZS  + (u64)NB_Z * NNODES * OUTD)
#define OFF_RK  (OFF_EPS + (u64)NB_Z * NNODES * OUTD)
#define OFF_SNR (OFF_RK + 16ull)

// ---------- f32x2 helpers ----------
__device__ __forceinline__ u64 pack2(float a, float b) {
    u64 r; asm("mov.b64 %0, {%1, %2};" : "=l"(r) : "r"(__float_as_int(a)), "r"(__float_as_int(b))); return r;
}
__device__ __forceinline__ void unpack2f(u64 v, float& a, float& b) {
    int x, y; asm("mov.b64 {%0, %1}, %2;" : "=r"(x), "=r"(y) : "l"(v));
    a = __int_as_float(x); b = __int_as_float(y);
}
__device__ __forceinline__ u64 fma2(u64 a, u64 b, u64 c) {
    u64 d; asm("fma.rn.f32x2 %0, %1, %2, %3;" : "=l"(d) : "l"(a), "l"(b), "l"(c)); return d;
}

// ---------- edge access (inline int64 detection) ----------
__device__ __forceinline__ int detect_w64(const int* __restrict__ ei) {
    return (ei[1] | ei[3] | ei[5] | ei[7] | ei[9] | ei[11] | ei[13] | ei[15]) == 0;
}
__device__ __forceinline__ int edge_src(const int* ei, int i, int w64) { return w64 ? ei[2 * i] : ei[i]; }
__device__ __forceinline__ int edge_dst(const int* ei, int i, int w64) { return w64 ? ei[2 * (NEDGES + i)] : ei[NEDGES + i]; }

// ---------- sgemm body (64x128 tile, BK=16, f32x2) -> g_h1 ----------
__device__ __forceinline__ void sgemm_body(const float* __restrict__ A, const float* __restrict__ B,
                                           int K, int bxx, int by, float* pool) {
    float (*As)[65]  = reinterpret_cast<float(*)[65]>(pool);
    float (*Bs)[128] = reinterpret_cast<float(*)[128]>(pool + 16 * 65);
    int tid = threadIdx.x;
    const float* Ab = A + (size_t)by * 64 * K;
    const float* Bb = B + bxx * 128;
    int aRow = tid >> 2, aCol = (tid & 3) * 4;
    int bRow = tid >> 5, bCol = (tid & 31) * 4;
    int ty = tid >> 4, tx = tid & 15;
    u64 acc2[4][4] = {};
    for (int k0 = 0; k0 < K; k0 += 16) {
        float4 a4 = *reinterpret_cast<const float4*>(Ab + (size_t)aRow * K + k0 + aCol);
        float4 b4a = *reinterpret_cast<const float4*>(Bb + (size_t)(k0 + bRow) * HID + bCol);
        float4 b4b = *reinterpret_cast<const float4*>(Bb + (size_t)(k0 + bRow + 8) * HID + bCol);
        __syncthreads();
        As[aCol + 0][aRow] = a4.x; As[aCol + 1][aRow] = a4.y;
        As[aCol + 2][aRow] = a4.z; As[aCol + 3][aRow] = a4.w;
        *reinterpret_cast<float4*>(&Bs[bRow][bCol]) = b4a;
        *reinterpret_cast<float4*>(&Bs[bRow + 8][bCol]) = b4b;
        __syncthreads();
#pragma unroll
        for (int kk = 0; kk < 16; kk++) {
            u64 b2[4];
#pragma unroll
            for (int p = 0; p < 4; p++) b2[p] = reinterpret_cast<const u64*>(&Bs[kk][tx * 8])[p];
#pragma unroll
            for (int i = 0; i < 4; i++) {
                float a = As[kk][ty * 4 + i];
                u64 a2 = pack2(a, a);
#pragma unroll
                for (int p = 0; p < 4; p++) acc2[i][p] = fma2(a2, b2[p], acc2[i][p]);
            }
        }
    }
#pragma unroll
    for (int i = 0; i < 4; i++) {
        size_t row = (size_t)by * 64 + ty * 4 + i;
        int col = bxx * 128 + tx * 8;
        float v[8];
#pragma unroll
        for (int p = 0; p < 4; p++) unpack2f(acc2[i][p], v[2 * p], v[2 * p + 1]);
        float4 o0 = {v[0], v[1], v[2], v[3]}, o1 = {v[4], v[5], v[6], v[7]};
        *reinterpret_cast<float4*>(&g_h1[row * HID + col]) = o0;
        *reinterpret_cast<float4*>(&g_h1[row * HID + col + 4]) = o1;
    }
}

// ========== K1: deg_count | we32/bewc | G | v,s0 | sgemm0 ==========
__global__ __launch_bounds__(256) void phase1_kernel(const int* __restrict__ ei,
                                                     const float* __restrict__ x,
                                                     const float* __restrict__ W1,
                                                     const float* __restrict__ We,
                                                     const float* __restrict__ be,
                                                     const float* __restrict__ Wmu,
                                                     const float* __restrict__ Wsig) {
    __shared__ float pool[16 * 65 + 16 * 128];
    __shared__ float tile[64][33];
    int bx = blockIdx.x, tid = threadIdx.x;
    if (bx < 512) {
        int w64 = detect_w64(ei);
        int i = bx * 256 + tid;
        atomicAdd(&g_deg[edge_dst(ei, i, w64)], 1);
    } else if (bx < 520) {
        int idx = (bx - 512) * 256 + tid;
        int i = idx >> 5, j = idx & 31;
        const float* W = (j < 16) ? Wmu : Wsig;
        int jj = j & 15;
        float acc = 0.0f;
#pragma unroll 8
        for (int k = 0; k < HID; k++) acc = fmaf(We[i * HID + k], W[k * 16 + jj], acc);
        g_we32[i * 32 + j] = acc * REWEIGHT;
    } else if (bx == 520) {
        if (tid < 32) {
            const float* W = (tid < 16) ? Wmu : Wsig;
            int jj = tid & 15;
            float acc = 0.0f;
            for (int k = 0; k < HID; k++) acc = fmaf(be[k], W[k * 16 + jj], acc);
            g_bewc[tid] = acc;
        }
    } else if (bx == 521) {
        // G = R^2 We We^T  (one block, tiled over k)
        float acc[4][4] = {};
        int i0 = (tid >> 4) * 4, j0 = (tid & 15) * 4;
        for (int k0 = 0; k0 < HID; k0 += 32) {
            __syncthreads();
            for (int l = tid; l < 2048; l += 256) {
                int r = l >> 5, kk = l & 31;
                tile[r][kk] = We[r * HID + k0 + kk];
            }
            __syncthreads();
#pragma unroll
            for (int kk = 0; kk < 32; kk++) {
                float a[4], b[4];
#pragma unroll
                for (int ii = 0; ii < 4; ii++) a[ii] = tile[i0 + ii][kk];
#pragma unroll
                for (int jj = 0; jj < 4; jj++) b[jj] = tile[j0 + jj][kk];
#pragma unroll
                for (int ii = 0; ii < 4; ii++)
#pragma unroll
                    for (int jj = 0; jj < 4; jj++) acc[ii][jj] = fmaf(a[ii], b[jj], acc[ii][jj]);
            }
        }
        const float R2 = REWEIGHT * REWEIGHT;
#pragma unroll
        for (int ii = 0; ii < 4; ii++)
#pragma unroll
            for (int jj = 0; jj < 4; jj++) g_G[(i0 + ii) * 64 + j0 + jj] = acc[ii][jj] * R2;
    } else if (bx == 522) {
        if (tid < 64) {
            float a = 0.0f;
            for (int c = 0; c < HID; c++) a = fmaf(We[tid * HID + c], be[c], a);
            g_v[tid] = 2.0f * REWEIGHT * a;
        } else if (tid == 64) {
            float s = 0.0f;
            for (int c = 0; c < HID; c++) s = fmaf(be[c], be[c], s);
            g_s0 = s;
        }
    } else {
        int bid = bx - 523;
        sgemm_body(x, W1, IN_CH, bid & 1, bid >> 1, pool);
    }
}

// ========== K2: dinv + scan + g_acc zero ==========
__global__ void dinv_scan_kernel() {
    __shared__ int sums[32];
    int tid = threadIdx.x, base = tid * 4;
    if (tid < 8) g_acc[tid] = 0.0f;
    int v[4], s = 0;
#pragma unroll
    for (int i = 0; i < 4; i++) {
        v[i] = g_deg[base + i];
        g_dinv[base + i] = rsqrtf((float)v[i] + 1.0f);
        s += v[i];
    }
    int lane = tid & 31, wid = tid >> 5, ss = s;
#pragma unroll
    for (int o = 1; o < 32; o <<= 1) { int t = __shfl_up_sync(~0u, ss, o); if (lane >= o) ss += t; }
    if (lane == 31) sums[wid] = ss;
    __syncthreads();
    if (wid == 0) {
        int w = sums[lane];
#pragma unroll
        for (int o = 1; o < 32; o <<= 1) { int t = __shfl_up_sync(~0u, w, o); if (lane >= o) w += t; }
        sums[lane] = w;
    }
    __syncthreads();
    int run = ss - s + (wid > 0 ? sums[wid - 1] : 0);
#pragma unroll
    for (int i = 0; i < 4; i++) { g_rowptr[base + i] = run; g_cursor[base + i] = run; run += v[i]; }
    if (tid == 1023) g_rowptr[NNODES] = run;
}

// ========== K3: csr_fill (packed cw) + deg re-zero ==========
__global__ __launch_bounds__(256) void csr_fill_kernel(const int* __restrict__ ei) {
    int i = blockIdx.x * 256 + threadIdx.x;
    int w64 = detect_w64(ei);
    int s = edge_src(ei, i, w64), d = edge_dst(ei, i, w64);
    int pos = atomicAdd(&g_cursor[d], 1);
    int2 cw; cw.x = s; cw.y = __float_as_int(g_dinv[s] * g_dinv[d]);
    g_cw[pos] = cw;
    if (i < NNODES) g_deg[i] = 0;
}

// ========== K4: prop256x(+thx,+sumsq) | propE64(+quad sumsq,+the32) ==========
__global__ __launch_bounds__(256) void phase4_kernel(const float* __restrict__ b1,
                                                     const float* __restrict__ e_noise,
                                                     const float* __restrict__ Wmu,
                                                     const float* __restrict__ Wsig) {
    __shared__ float sh[2][256];
    __shared__ float red[2][4][32];
    __shared__ float ws[8];
    __shared__ float shpe[8][64];
    int bx = blockIdx.x, tid = threadIdx.x;
    if (bx < 2048) {
        int g = tid >> 7;
        int n = bx * 2 + g;
        int c2 = tid & 127;
        const float2* hb = reinterpret_cast<const float2*>(g_h1);
        int start = g_rowptr[n], end = g_rowptr[n + 1];
        float d = g_dinv[n];
        float2 self = hb[n * 128 + c2];
        float ax = self.x * d * d, ay = self.y * d * d;
        for (int j = start; j < end; j++) {
            int2 cw = g_cw[j];
            float w = __int_as_float(cw.y);
            float2 v = hb[cw.x * 128 + c2];
            ax = fmaf(w, v.x, ax); ay = fmaf(w, v.y, ay);
        }
        float2 bb = reinterpret_cast<const float2*>(b1)[c2];
        ax = fmaxf(ax + bb.x, 0.0f); ay = fmaxf(ay + bb.y, 0.0f);
        float2 o = {ax, ay};
        reinterpret_cast<float2*>(g_hx)[n * 128 + c2] = o;
        sh[g][c2 * 2] = ax; sh[g][c2 * 2 + 1] = ay;
        float s = ax * ax + ay * ay;
#pragma unroll
        for (int of = 16; of > 0; of >>= 1) s += __shfl_down_sync(~0u, s, of);
        if ((tid & 31) == 0) ws[tid >> 5] = s;
        __syncthreads();
        if (tid == 0) atomicAdd(&g_acc[0], ws[0] + ws[1] + ws[2] + ws[3]);
        if (tid == 128) atomicAdd(&g_acc[0], ws[4] + ws[5] + ws[6] + ws[7]);
        // thx = hx_row @ [Wmu|Wsig]
        int seg = (tid >> 5) & 3, c0 = tid & 31;
        const float* W = (c0 < 16) ? Wmu : Wsig;
        int cc = c0 & 15;
        float t = 0.0f;
        int k0 = seg * 64;
#pragma unroll 8
        for (int k = k0; k < k0 + 64; k++) t = fmaf(sh[g][k], W[k * 16 + cc], t);
        red[g][seg][c0] = t;
        __syncthreads();
        if ((tid & 96) == 0)
            g_thx[n * 32 + c0] = red[g][0][c0] + red[g][1][c0] + red[g][2][c0] + red[g][3][c0];
    } else {
        int w = (bx - 2048) * 8 + (tid >> 5);      // (b,n) per warp
        int wg = tid >> 5, lane = tid & 31;
        int b = w >> 12, n = w & (NNODES - 1);
        const float2* eb = reinterpret_cast<const float2*>(e_noise);
        int start = g_rowptr[n], end = g_rowptr[n + 1];
        float d = g_dinv[n];
        float2 self = eb[(size_t)(b * NNODES + n) * 32 + lane];
        float px = self.x * d * d, py = self.y * d * d;
        for (int j = start; j < end; j++) {
            int2 cw = g_cw[j];
            float wt = __int_as_float(cw.y);
            float2 v = eb[(size_t)(b * NNODES + cw.x) * 32 + lane];
            px = fmaf(wt, v.x, px); py = fmaf(wt, v.y, py);
        }
        shpe[wg][lane * 2] = px; shpe[wg][lane * 2 + 1] = py;
        __syncwarp();
        // sumsq via quadratic form: pe^T G pe + v.pe + s0
        float tx = 0.0f, ty = 0.0f;
#pragma unroll 8
        for (int i = 0; i < 64; i++) {
            float a = shpe[wg][i];
            float2 g2 = reinterpret_cast<const float2*>(g_G)[i * 32 + lane];
            tx = fmaf(a, g2.x, tx); ty = fmaf(a, g2.y, ty);
        }
        float2 gv = reinterpret_cast<const float2*>(g_v)[lane];
        float partial = (tx + gv.x) * px + (ty + gv.y) * py;
#pragma unroll
        for (int of = 16; of > 0; of >>= 1) partial += __shfl_down_sync(~0u, partial, of);
        if (lane == 0) atomicAdd(&g_acc[1 + b], partial + g_s0);
        // the32 = pe @ we32  (we32 already includes R)
        float a32 = 0.0f;
#pragma unroll 8
        for (int k = 0; k < 64; k++)
            a32 = fmaf(shpe[wg][k], g_we32[k * 32 + lane], a32);
        g_the[(size_t)w * 32 + lane] = a32;
    }
}

// ========== K5: t = thx + the + bewc (elementwise) ==========
__global__ void tassemble_kernel() {
    int i = blockIdx.x * 1024 + threadIdx.x;
    int row = i >> 5, c = i & 31;
    int n = row & (NNODES - 1);
    g_t[i] = g_thx[n * 32 + c] + g_the[i] + g_bewc[c];
}

// ========== K6: mu/sig = P(t) + bias, fused z ==========
__global__ void prop32z_kernel(const float* __restrict__ bmu, const float* __restrict__ bsig,
                               const float* __restrict__ eps, float* __restrict__ out) {
    int warp = (blockIdx.x * blockDim.x + threadIdx.x) >> 5;
    int lane = threadIdx.x & 31;
    int b = warp >> 12, n = warp & (NNODES - 1);
    const float* tb = g_t + (size_t)b * NNODES * 32;
    float d = g_dinv[n];
    float acc = tb[(size_t)n * 32 + lane] * d * d;
    int start = g_rowptr[n], end = g_rowptr[n + 1];
    for (int j = start; j < end; j++) {
        int2 cw = g_cw[j];
        acc = fmaf(__int_as_float(cw.y), tb[(size_t)cw.x * 32 + lane], acc);
    }
    float biased = acc + ((lane < 16) ? bmu[lane] : bsig[lane - 16]);
    size_t base = ((size_t)b * NNODES + n) * OUTD;
    if (lane < 16) out[OFF_MU + base + lane] = biased;
    else           out[OFF_SIG + base + (lane - 16)] = biased;
    if (b >= 2) {
        float sig = __shfl_sync(~0u, biased, lane + 16);
        if (lane < 16) {
            size_t zi = ((size_t)(b - 2) * NNODES + n) * OUTD + lane;
            float e = eps[zi];
            float zv = fmaf(e, __expf(0.5f * sig), biased);
            out[OFF_Z + zi] = zv;
            out[OFF_ZS + zi] = zv;
            out[OFF_EPS + zi] = e;
        }
    }
}

// ========== K7: adj = sigmoid(z z^T) + snr/rk tail ==========
__device__ __forceinline__ float sigmoid1(float x) {
    float e = __expf(-x);
    float d = 1.0f + e;
    float r; asm("rcp.approx.f32 %0, %1;" : "=f"(r) : "f"(d));
    return r;
}

__global__ __launch_bounds__(256) void adj_kernel(const float* __restrict__ rk_lgt,
                                                  float* __restrict__ out) {
    int tid = threadIdx.x;
    if (blockIdx.x == 0 && blockIdx.y == 0 && blockIdx.z == 0 && tid < 32) {
        if (tid < 5) out[OFF_SNR + tid] = g_acc[0] / g_acc[1 + tid];
        if (tid < 16) out[OFF_RK + tid] = sqrtf(1.0f / (1.0f + expf(-rk_lgt[tid])));
    }
    const float* zb = out + OFF_Z + (size_t)blockIdx.z * NNODES * OUTD;
    float* ab = out + OFF_ADJ + (size_t)blockIdx.z * NNODES * NNODES;
    __shared__ float ziT[16][132];
    __shared__ float zjT[16][132];
    int i0 = blockIdx.y * 128, j0 = blockIdx.x * 128;
#pragma unroll
    for (int rnd = 0; rnd < 2; rnd++) {
        int L4 = tid + rnd * 256;
        float4 a = *reinterpret_cast<const float4*>(zb + (size_t)i0 * 16 + L4 * 4);
        float4 b = *reinterpret_cast<const float4*>(zb + (size_t)j0 * 16 + L4 * 4);
        int r = L4 >> 2, k0 = (L4 & 3) * 4;
        ziT[k0 + 0][r] = a.x; ziT[k0 + 1][r] = a.y; ziT[k0 + 2][r] = a.z; ziT[k0 + 3][r] = a.w;
        zjT[k0 + 0][r] = b.x; zjT[k0 + 1][r] = b.y; zjT[k0 + 2][r] = b.z; zjT[k0 + 3][r] = b.w;
    }
    __syncthreads();
    int tx = tid & 15, ty = tid >> 4;
    u64 acc2[8][4] = {};
#pragma unroll
    for (int k = 0; k < 16; k++) {
        float4 b0 = *reinterpret_cast<const float4*>(&zjT[k][tx * 8]);
        float4 b1 = *reinterpret_cast<const float4*>(&zjT[k][tx * 8 + 4]);
        u64 b2[4];
        b2[0] = pack2(b0.x, b0.y); b2[1] = pack2(b0.z, b0.w);
        b2[2] = pack2(b1.x, b1.y); b2[3] = pack2(b1.z, b1.w);
        float4 a0 = *reinterpret_cast<const float4*>(&ziT[k][ty * 8]);
        float4 a1 = *reinterpret_cast<const float4*>(&ziT[k][ty * 8 + 4]);
        float av[8] = {a0.x, a0.y, a0.z, a0.w, a1.x, a1.y, a1.z, a1.w};
#pragma unroll
        for (int i = 0; i < 8; i++) {
            u64 a2 = pack2(av[i], av[i]);
#pragma unroll
            for (int p = 0; p < 4; p++) acc2[i][p] = fma2(a2, b2[p], acc2[i][p]);
        }
    }
#pragma unroll
    for (int i = 0; i < 8; i++) {
        float v[8];
#pragma unroll
        for (int p = 0; p < 4; p++) unpack2f(acc2[i][p], v[2 * p], v[2 * p + 1]);
        float4 o0, o1;
        o0.x = sigmoid1(v[0]); o0.y = sigmoid1(v[1]); o0.z = sigmoid1(v[2]); o0.w = sigmoid1(v[3]);
        o1.x = sigmoid1(v[4]); o1.y = sigmoid1(v[5]); o1.z = sigmoid1(v[6]); o1.w = sigmoid1(v[7]);
        float* row = ab + (size_t)(i0 + ty * 8 + i) * NNODES + j0 + tx * 8;
        *reinterpret_cast<float4*>(row) = o0;
        *reinterpret_cast<float4*>(row + 4) = o1;
    }
}

// =================================================================================
extern "C" void kernel_launch(void* const* d_in, const int* in_sizes, int n_in,
                              void* d_out, int out_size) {
    (void)in_sizes; (void)n_in; (void)out_size;
    const float* x       = (const float*)d_in[0];
    const int*   ei      = (const int*)d_in[1];
    const float* e_noise = (const float*)d_in[2];
    const float* eps     = (const float*)d_in[3];
    const float* W1      = (const float*)d_in[4];
    const float* b1      = (const float*)d_in[5];
    const float* We      = (const float*)d_in[6];
    const float* be      = (const float*)d_in[7];
    const float* Wmu     = (const float*)d_in[8];
    const float* bmu     = (const float*)d_in[9];
    const float* Wsig    = (const float*)d_in[10];
    const float* bsig    = (const float*)d_in[11];
    const float* rk_lgt  = (const float*)d_in[12];
    float* out = (float*)d_out;

    phase1_kernel<<<523 + 128, 256>>>(ei, x, W1, We, be, Wmu, Wsig);
    dinv_scan_kernel<<<1, 1024>>>();
    csr_fill_kernel<<<512, 256>>>(ei);
    phase4_kernel<<<2048 + 2560, 256>>>(b1, e_noise, Wmu, Wsig);
    tassemble_kernel<<<NB_E * NNODES * 32 / 1024, 1024>>>();
    prop32z_kernel<<<2560, 256>>>(bmu, bsig, eps, out);
    adj_kernel<<<dim3(32, 32, NB_Z), 256>>>(rk_lgt, out);
}